// round 15
// baseline (speedup 1.0000x reference)
#include <cuda_runtime.h>
#include <cuda_fp16.h>
#include <math_constants.h>
#include <cstdint>

#define BDIM 8192
#define DDIM 512
#define MARGIN 0.2f
#define NRB 32                    // 256-row blocks
#define NCB 64                    // 128-col blocks
#define NTILE 1056                // sum_R (64 - 2R)
#define NSLOT 96                  // 64 row-side + 32 col-side partial slots
#define HPMAXM 48
#define HPBYTES (HPMAXM * DDIM * 2)

// ---------------- scratch ----------------
__device__ __align__(16) half g_embh[(size_t)BDIM * DDIM];   // fp16 embeddings (8 MB)
__device__ float g_sq[BDIM];
__device__ float g_hp2[BDIM];
__device__ float g_all2[(size_t)NSLOT * BDIM];
__device__ float g_semi2[(size_t)NSLOT * BDIM];
__device__ float g_loss[BDIM];
__device__ int   g_ccnt[512];
__device__ int   g_cidx[512 * BDIM];

__device__ __forceinline__ uint32_t pack_h2(float x, float y) {
    half2 h = __floats2half2_rn(x, y);
    return *reinterpret_cast<uint32_t*>(&h);
}

// ---------------- prep: fp16 convert + sqnorm + init ----------------
__global__ void __launch_bounds__(128) prep_kernel(const float* __restrict__ emb) {
    const int i = blockIdx.x;
    const int tid = threadIdx.x;
    if (i < 4) g_ccnt[i * 128 + tid] = 0;
    if (tid == 0) g_hp2[i] = -CUDART_INF_F;
    float4 v = ((const float4*)(emb + (size_t)i * DDIM))[tid];
    ((uint2*)(g_embh + (size_t)i * DDIM))[tid] =
        make_uint2(pack_h2(v.x, v.y), pack_h2(v.z, v.w));
    float s = v.x * v.x + v.y * v.y + v.z * v.z + v.w * v.w;
    #pragma unroll
    for (int o = 16; o > 0; o >>= 1) s += __shfl_down_sync(0xFFFFFFFF, s, o);
    __shared__ float ws[4];
    if ((tid & 31) == 0) ws[tid >> 5] = s;
    __syncthreads();
    if (tid == 0) g_sq[i] = ws[0] + ws[1] + ws[2] + ws[3];
}

// ---------------- init partial-min arrays to +inf ----------------
__global__ void __launch_bounds__(256) init_partials() {
    const int idx = blockIdx.x * 256 + threadIdx.x;
    const float4 inf4 = make_float4(CUDART_INF_F, CUDART_INF_F, CUDART_INF_F, CUDART_INF_F);
    ((float4*)g_all2)[idx] = inf4;
    ((float4*)g_semi2)[idx] = inf4;
}

__global__ void scatter_cls(const int* __restrict__ labels) {
    int i = blockIdx.x * blockDim.x + threadIdx.x;
    if (i < BDIM) {
        int c = labels[i];
        int s = atomicAdd(&g_ccnt[c], 1);
        g_cidx[c * BDIM + s] = i;
    }
}

// ---------------- hardest positive: one block per class, 4-way j ILP ----------------
__global__ void __launch_bounds__(256) hp_kernel() {
    extern __shared__ uint32_t sh[];   // [m][256] half2 words
    __shared__ int s_idx[HPMAXM];
    __shared__ float s_sq[HPMAXM];

    const int c = blockIdx.x;
    const int cnt = min(g_ccnt[c], HPMAXM);
    const int tid = threadIdx.x;

    for (int m = tid; m < cnt; m += 256) {
        const int gi = g_cidx[c * BDIM + m];
        s_idx[m] = gi;
        s_sq[m] = g_sq[gi];
    }
    __syncthreads();
    for (int idx = tid; idx < cnt * 64; idx += 256) {
        const int m = idx >> 6, f = idx & 63;
        uint4 v = ((const uint4*)(g_embh + (size_t)s_idx[m] * DDIM))[f];
        *(uint4*)&sh[m * 256 + f * 4] = v;
    }
    __syncthreads();

    const int wid = tid >> 5, lane = tid & 31;
    for (int i = wid; i < cnt - 1; i += 8) {
        float2 a[8];
        #pragma unroll
        for (int q = 0; q < 8; q++) {
            half2 h = *(half2*)&sh[i * 256 + q * 32 + lane];
            a[q] = __half22float2(h);
        }
        const float sqi = s_sq[i];
        const int gi = s_idx[i];
        for (int j = i + 1; j < cnt; j += 4) {
            int jj[4];
            #pragma unroll
            for (int u = 0; u < 4; u++) jj[u] = (j + u < cnt) ? j + u : j;
            float p[4] = {0.f, 0.f, 0.f, 0.f};
            #pragma unroll
            for (int q = 0; q < 8; q++) {
                #pragma unroll
                for (int u = 0; u < 4; u++) {
                    float2 b = __half22float2(*(half2*)&sh[jj[u] * 256 + q * 32 + lane]);
                    p[u] += a[q].x * b.x + a[q].y * b.y;
                }
            }
            #pragma unroll
            for (int o = 16; o > 0; o >>= 1) {
                #pragma unroll
                for (int u = 0; u < 4; u++)
                    p[u] += __shfl_xor_sync(0xFFFFFFFF, p[u], o);
            }
            if (lane == 0) {
                #pragma unroll
                for (int u = 0; u < 4; u++) {
                    if (j + u < cnt) {
                        const float d2 = sqi + s_sq[jj[u]] - 2.f * p[u];
                        if (d2 > 0.f) {
                            atomicMax((int*)&g_hp2[gi], __float_as_int(d2));
                            atomicMax((int*)&g_hp2[s_idx[jj[u]]], __float_as_int(d2));
                        }
                    }
                }
            }
        }
    }
}

// ---------------- mma / cp.async helpers ----------------
__device__ __forceinline__ void mma16(float* c, const uint32_t* a, const uint32_t* b) {
    asm volatile(
        "mma.sync.aligned.m16n8k16.row.col.f32.f16.f16.f32 "
        "{%0,%1,%2,%3},{%4,%5,%6,%7},{%8,%9},{%0,%1,%2,%3};"
        : "+f"(c[0]), "+f"(c[1]), "+f"(c[2]), "+f"(c[3])
        : "r"(a[0]), "r"(a[1]), "r"(a[2]), "r"(a[3]), "r"(b[0]), "r"(b[1]));
}
__device__ __forceinline__ void ldsm4(uint32_t& r0, uint32_t& r1, uint32_t& r2, uint32_t& r3,
                                      uint32_t addr) {
    asm volatile("ldmatrix.sync.aligned.m8n8.x4.shared.b16 {%0,%1,%2,%3}, [%4];"
                 : "=r"(r0), "=r"(r1), "=r"(r2), "=r"(r3) : "r"(addr));
}
__device__ __forceinline__ void cpa16(uint32_t dst, const void* src) {
    asm volatile("cp.async.cg.shared.global [%0], [%1], 16;" :: "r"(dst), "l"(src));
}
__device__ __forceinline__ void cpa_commit() {
    asm volatile("cp.async.commit_group;" ::: "memory");
}
template <int N>
__device__ __forceinline__ void cpa_wait() {
    asm volatile("cp.async.wait_group %0;" :: "n"(N) : "memory");
}

#define HSTRIDE 40                        // halfs per row (80 B)
#define ABUF (256 * 80)                   // A stage bytes = 20480
#define BBUF (128 * 80)                   // B stage bytes = 10240
#define NSTAGE 4
#define GEMM_DYN (NSTAGE * (ABUF + BBUF)) // 122880 bytes

// ---------------- fp16 mma GEMM: 256x128 tile, 512 thr (16 warps), 1 CTA/SM ----------------
__global__ void __launch_bounds__(512, 1) gemm_mma(const int* __restrict__ labels) {
    extern __shared__ __align__(16) char dynsm[];
    __shared__ int s_rall[256], s_rsem[256], s_call[128], s_csem[128];
    __shared__ float s_sqi[256], s_sqj[128], s_hp2i[256], s_hp2j[128];
    __shared__ int s_li[256], s_lj[128];

    // decode tile: R in 0..31, C in 2R..63
    int rem = blockIdx.x, R = 0;
    while (rem >= NCB - 2 * R) { rem -= NCB - 2 * R; R++; }
    const int C = 2 * R + rem;
    const int rowBase = R * 256;
    const int colBase = C * 128;

    const int tid = threadIdx.x;
    const int wid = tid >> 5;
    const int lane = tid & 31;
    const int g = lane >> 2;
    const int t = lane & 3;
    const int mBase = (wid >> 2) * 64;   // 4 m-groups of 64 rows
    const int nBase = (wid & 3) * 32;    // 4 n-groups of 32 cols

    if (tid < 256) {
        s_rall[tid] = 0x7F800000; s_rsem[tid] = 0x7F800000;
        const int gi = rowBase + tid;
        s_sqi[tid] = g_sq[gi]; s_hp2i[tid] = g_hp2[gi]; s_li[tid] = labels[gi];
    }
    if (tid < 128) {
        s_call[tid] = 0x7F800000; s_csem[tid] = 0x7F800000;
        const int gj = colBase + tid;
        s_sqj[tid] = g_sq[gj]; s_hp2j[tid] = g_hp2[gj]; s_lj[tid] = labels[gj];
    }

    float acc[4][4][4];
    #pragma unroll
    for (int mf = 0; mf < 4; mf++)
        #pragma unroll
        for (int nf = 0; nf < 4; nf++)
            #pragma unroll
            for (int r = 0; r < 4; r++) acc[mf][nf][r] = 0.f;

    // producer mapping: A 1024 segs (2/thread), B 512 segs (1/thread)
    const int prow = tid >> 2;          // 0..127
    const int pseg = tid & 3;
    const uint32_t AshD = (uint32_t)__cvta_generic_to_shared(dynsm);
    const uint32_t BshD = AshD + NSTAGE * ABUF;
    const half* srcA = g_embh + (size_t)(rowBase + prow) * DDIM + pseg * 8;
    const half* srcB = g_embh + (size_t)(colBase + prow) * DDIM + pseg * 8;
    const uint32_t dstOff = prow * 80 + pseg * 16;

    // ldmatrix per-lane base addresses
    const int arow = (lane & 7) + (((lane >> 3) & 1) << 3);
    const int acol = (lane >> 4) << 3;
    const int brow = ((lane >> 4) << 3) + (lane & 7);
    const int bcol = ((lane >> 3) & 1) << 3;
    const uint32_t aBase0 = AshD + (((mBase + arow) * HSTRIDE + acol) << 1);
    const uint32_t bBase0 = BshD + (((nBase + brow) * HSTRIDE + bcol) << 1);

    auto issue = [&](int c) {
        const int st = c & (NSTAGE - 1);
        const int k0 = c * 32;
        cpa16(AshD + st * ABUF + dstOff, srcA + (size_t)0 * DDIM + k0);
        cpa16(AshD + st * ABUF + dstOff + 128 * 80, srcA + (size_t)128 * DDIM + k0);
        cpa16(BshD + st * BBUF + dstOff, srcB + k0);
        cpa_commit();
    };

    issue(0); issue(1); issue(2);

    #pragma unroll
    for (int c = 0; c < 16; c++) {
        if (c < 14)       cpa_wait<2>();
        else if (c == 14) cpa_wait<1>();
        else              cpa_wait<0>();
        __syncthreads();
        if (c + 3 < 16) issue(c + 3);

        const int st = c & (NSTAGE - 1);
        #pragma unroll
        for (int s = 0; s < 2; s++) {
            uint32_t bf[4][2];
            #pragma unroll
            for (int q = 0; q < 2; q++) {
                const uint32_t baddr = bBase0 + st * BBUF + ((q * 16 * HSTRIDE + s * 16) << 1);
                ldsm4(bf[2 * q][0], bf[2 * q][1], bf[2 * q + 1][0], bf[2 * q + 1][1], baddr);
            }
            #pragma unroll
            for (int mf = 0; mf < 4; mf++) {
                uint32_t af[4];
                const uint32_t aaddr = aBase0 + st * ABUF + ((mf * 16 * HSTRIDE + s * 16) << 1);
                ldsm4(af[0], af[1], af[2], af[3], aaddr);
                #pragma unroll
                for (int nf = 0; nf < 4; nf++)
                    mma16(acc[mf][nf], af, bf[nf]);
            }
        }
    }

    // ---------------- epilogue ----------------
    float rAll[4][2], rSem[4][2], cAll[4][2], cSem[4][2];
    #pragma unroll
    for (int x = 0; x < 4; x++)
        #pragma unroll
        for (int y = 0; y < 2; y++) {
            rAll[x][y] = CUDART_INF_F; rSem[x][y] = CUDART_INF_F;
            cAll[x][y] = CUDART_INF_F; cSem[x][y] = CUDART_INF_F;
        }

    #pragma unroll
    for (int mf = 0; mf < 4; mf++) {
        #pragma unroll
        for (int h = 0; h < 2; h++) {
            const int rloc = mBase + mf * 16 + g + 8 * h;
            const float sqi = s_sqi[rloc];
            const int li = s_li[rloc];
            const float hp2i = s_hp2i[rloc];
            #pragma unroll
            for (int nf = 0; nf < 4; nf++) {
                #pragma unroll
                for (int b = 0; b < 2; b++) {
                    const int cloc = nBase + nf * 8 + 2 * t + b;
                    const float dot = acc[mf][nf][2 * h + b];
                    const float v = fmaxf(sqi + s_sqj[cloc] - 2.f * dot, 0.f);
                    const bool neg = (li != s_lj[cloc]);
                    const float va = neg ? v : CUDART_INF_F;
                    const float vsr = (neg && v > hp2i) ? v : CUDART_INF_F;
                    const float vsc = (neg && v > s_hp2j[cloc]) ? v : CUDART_INF_F;
                    rAll[mf][h] = fminf(rAll[mf][h], va);
                    rSem[mf][h] = fminf(rSem[mf][h], vsr);
                    cAll[nf][b] = fminf(cAll[nf][b], va);
                    cSem[nf][b] = fminf(cSem[nf][b], vsc);
                }
            }
        }
    }

    #pragma unroll
    for (int mf = 0; mf < 4; mf++)
        #pragma unroll
        for (int h = 0; h < 2; h++) {
            float a = rAll[mf][h], s = rSem[mf][h];
            #pragma unroll
            for (int o = 1; o < 4; o <<= 1) {
                a = fminf(a, __shfl_xor_sync(0xFFFFFFFF, a, o));
                s = fminf(s, __shfl_xor_sync(0xFFFFFFFF, s, o));
            }
            if (t == 0) {
                const int rloc = mBase + mf * 16 + g + 8 * h;
                atomicMin(&s_rall[rloc], __float_as_int(a));
                atomicMin(&s_rsem[rloc], __float_as_int(s));
            }
        }
    #pragma unroll
    for (int nf = 0; nf < 4; nf++)
        #pragma unroll
        for (int b = 0; b < 2; b++) {
            float a = cAll[nf][b], s = cSem[nf][b];
            #pragma unroll
            for (int o = 4; o < 32; o <<= 1) {
                a = fminf(a, __shfl_xor_sync(0xFFFFFFFF, a, o));
                s = fminf(s, __shfl_xor_sync(0xFFFFFFFF, s, o));
            }
            if (g == 0) {
                const int cloc = nBase + nf * 8 + 2 * t + b;
                atomicMin(&s_call[cloc], __float_as_int(a));
                atomicMin(&s_csem[cloc], __float_as_int(s));
            }
        }
    __syncthreads();

    // row-side -> slot C; col-side -> slot 64+R (unwritten slots pre-inited to +inf)
    if (tid < 256) {
        g_all2[(size_t)C * BDIM + rowBase + tid] = __int_as_float(s_rall[tid]);
        g_semi2[(size_t)C * BDIM + rowBase + tid] = __int_as_float(s_rsem[tid]);
    }
    if (tid < 128) {
        g_all2[(size_t)(64 + R) * BDIM + colBase + tid] = __int_as_float(s_call[tid]);
        g_semi2[(size_t)(64 + R) * BDIM + colBase + tid] = __int_as_float(s_csem[tid]);
    }
}

// ---------------- per-row finish ----------------
__global__ void __launch_bounds__(256) rowfinish() {
    const int r = blockIdx.x * 256 + threadIdx.x;
    float mA = CUDART_INF_F, mS = CUDART_INF_F;
    #pragma unroll 8
    for (int tt = 0; tt < NSLOT; tt++) {
        mA = fminf(mA, g_all2[(size_t)tt * BDIM + r]);
        mS = fminf(mS, g_semi2[(size_t)tt * BDIM + r]);
    }
    const float hn2 = (mS < CUDART_INF_F) ? mS : mA;
    const float hp2 = g_hp2[r];
    float loss = 0.f;
    if (hp2 >= 0.f) {
        const float l = sqrtf(hp2) - sqrtf(hn2) + MARGIN;
        loss = fmaxf(l, 0.f);
    }
    g_loss[r] = loss;
}

__global__ void __launch_bounds__(256) final_reduce(float* __restrict__ out) {
    const int tid = threadIdx.x;
    float acc = 0.f;
    for (int k = tid; k < BDIM; k += 256) acc += g_loss[k];
    __shared__ float s[256];
    s[tid] = acc;
    __syncthreads();
    #pragma unroll
    for (int st = 128; st > 0; st >>= 1) {
        if (tid < st) s[tid] += s[tid + st];
        __syncthreads();
    }
    if (tid == 0) out[0] = s[0] / (float)BDIM;
}

// ---------------- launch ----------------
extern "C" void kernel_launch(void* const* d_in, const int* in_sizes, int n_in,
                              void* d_out, int out_size) {
    const float* emb = (const float*)d_in[0];
    const int* labels = (const int*)d_in[1];
    float* out = (float*)d_out;

    cudaFuncSetAttribute(hp_kernel, cudaFuncAttributeMaxDynamicSharedMemorySize, HPBYTES);
    cudaFuncSetAttribute(gemm_mma, cudaFuncAttributeMaxDynamicSharedMemorySize, GEMM_DYN);

    prep_kernel<<<BDIM, 128>>>(emb);
    init_partials<<<NSLOT * BDIM / 1024, 256>>>();
    scatter_cls<<<BDIM / 256, 256>>>(labels);
    hp_kernel<<<512, 256, HPBYTES>>>();
    gemm_mma<<<NTILE, 512, GEMM_DYN>>>(labels);
    rowfinish<<<BDIM / 256, 256>>>();
    final_reduce<<<1, 256>>>(out);
}

// round 17
// speedup vs baseline: 1.1597x; 1.1597x over previous
#include <cuda_runtime.h>
#include <cuda_fp16.h>
#include <math_constants.h>
#include <cstdint>

#define BDIM 8192
#define DDIM 512
#define MARGIN 0.2f
#define TILES 64
#define NTRI  (TILES * (TILES + 1) / 2)
#define HPMAXM 48
#define HPBYTES (HPMAXM * DDIM * 2)

// ---------------- scratch ----------------
__device__ __align__(16) half g_embh[(size_t)BDIM * DDIM];   // fp16 embeddings (8 MB)
__device__ float g_sq[BDIM];
__device__ float g_hp2[BDIM];
__device__ float g_all2[TILES * BDIM];
__device__ float g_semi2[TILES * BDIM];
__device__ float g_loss[BDIM];
__device__ int   g_ccnt[512];
__device__ int   g_cidx[512 * BDIM];

__device__ __forceinline__ uint32_t pack_h2(float x, float y) {
    half2 h = __floats2half2_rn(x, y);
    return *reinterpret_cast<uint32_t*>(&h);
}

// ---------------- prep: fp16 convert + sqnorm + init ----------------
__global__ void __launch_bounds__(128) prep_kernel(const float* __restrict__ emb) {
    const int i = blockIdx.x;
    const int tid = threadIdx.x;
    if (i < 4) g_ccnt[i * 128 + tid] = 0;
    if (tid == 0) g_hp2[i] = -CUDART_INF_F;
    float4 v = ((const float4*)(emb + (size_t)i * DDIM))[tid];
    ((uint2*)(g_embh + (size_t)i * DDIM))[tid] =
        make_uint2(pack_h2(v.x, v.y), pack_h2(v.z, v.w));
    float s = v.x * v.x + v.y * v.y + v.z * v.z + v.w * v.w;
    #pragma unroll
    for (int o = 16; o > 0; o >>= 1) s += __shfl_down_sync(0xFFFFFFFF, s, o);
    __shared__ float ws[4];
    if ((tid & 31) == 0) ws[tid >> 5] = s;
    __syncthreads();
    if (tid == 0) g_sq[i] = ws[0] + ws[1] + ws[2] + ws[3];
}

__global__ void scatter_cls(const int* __restrict__ labels) {
    int i = blockIdx.x * blockDim.x + threadIdx.x;
    if (i < BDIM) {
        int c = labels[i];
        int s = atomicAdd(&g_ccnt[c], 1);
        g_cidx[c * BDIM + s] = i;
    }
}

// ---------------- hardest positive: one block per class, 4-way j ILP, LDS.64 ----------------
__global__ void __launch_bounds__(256) hp_kernel() {
    extern __shared__ uint32_t sh[];   // [m][256] half2 words, contiguous rows
    __shared__ int s_idx[HPMAXM];
    __shared__ float s_sq[HPMAXM];

    const int c = blockIdx.x;
    const int cnt = min(g_ccnt[c], HPMAXM);
    const int tid = threadIdx.x;

    for (int m = tid; m < cnt; m += 256) {
        const int gi = g_cidx[c * BDIM + m];
        s_idx[m] = gi;
        s_sq[m] = g_sq[gi];
    }
    __syncthreads();
    for (int idx = tid; idx < cnt * 64; idx += 256) {
        const int m = idx >> 6, f = idx & 63;
        uint4 v = ((const uint4*)(g_embh + (size_t)s_idx[m] * DDIM))[f];
        *(uint4*)&sh[m * 256 + f * 4] = v;
    }
    __syncthreads();

    const int wid = tid >> 5, lane = tid & 31;
    for (int i = wid; i < cnt - 1; i += 8) {
        // lane owns words: grp*64 + lane*2 + {0,1}, grp=0..3  (dot is order-agnostic)
        float2 a[8];
        #pragma unroll
        for (int q = 0; q < 4; q++) {
            uint2 w = *(uint2*)&sh[i * 256 + q * 64 + lane * 2];
            a[2 * q]     = __half22float2(*(half2*)&w.x);
            a[2 * q + 1] = __half22float2(*(half2*)&w.y);
        }
        const float sqi = s_sq[i];
        const int gi = s_idx[i];
        for (int j = i + 1; j < cnt; j += 4) {
            int jj[4];
            #pragma unroll
            for (int u = 0; u < 4; u++) jj[u] = (j + u < cnt) ? j + u : j;
            float p[4] = {0.f, 0.f, 0.f, 0.f};
            #pragma unroll
            for (int q = 0; q < 4; q++) {
                #pragma unroll
                for (int u = 0; u < 4; u++) {
                    uint2 w = *(uint2*)&sh[jj[u] * 256 + q * 64 + lane * 2];
                    float2 b0 = __half22float2(*(half2*)&w.x);
                    float2 b1 = __half22float2(*(half2*)&w.y);
                    p[u] += a[2 * q].x * b0.x + a[2 * q].y * b0.y;
                    p[u] += a[2 * q + 1].x * b1.x + a[2 * q + 1].y * b1.y;
                }
            }
            #pragma unroll
            for (int o = 16; o > 0; o >>= 1) {
                #pragma unroll
                for (int u = 0; u < 4; u++)
                    p[u] += __shfl_xor_sync(0xFFFFFFFF, p[u], o);
            }
            if (lane == 0) {
                #pragma unroll
                for (int u = 0; u < 4; u++) {
                    if (j + u < cnt) {
                        const float d2 = sqi + s_sq[jj[u]] - 2.f * p[u];
                        if (d2 > 0.f) {
                            atomicMax((int*)&g_hp2[gi], __float_as_int(d2));
                            atomicMax((int*)&g_hp2[s_idx[jj[u]]], __float_as_int(d2));
                        }
                    }
                }
            }
        }
    }
}

// ---------------- mma / cp.async helpers ----------------
__device__ __forceinline__ void mma16(float* c, const uint32_t* a, const uint32_t* b) {
    asm volatile(
        "mma.sync.aligned.m16n8k16.row.col.f32.f16.f16.f32 "
        "{%0,%1,%2,%3},{%4,%5,%6,%7},{%8,%9},{%0,%1,%2,%3};"
        : "+f"(c[0]), "+f"(c[1]), "+f"(c[2]), "+f"(c[3])
        : "r"(a[0]), "r"(a[1]), "r"(a[2]), "r"(a[3]), "r"(b[0]), "r"(b[1]));
}
__device__ __forceinline__ void ldsm4(uint32_t& r0, uint32_t& r1, uint32_t& r2, uint32_t& r3,
                                      uint32_t addr) {
    asm volatile("ldmatrix.sync.aligned.m8n8.x4.shared.b16 {%0,%1,%2,%3}, [%4];"
                 : "=r"(r0), "=r"(r1), "=r"(r2), "=r"(r3) : "r"(addr));
}
__device__ __forceinline__ void cpa16(uint32_t dst, const void* src) {
    asm volatile("cp.async.cg.shared.global [%0], [%1], 16;" :: "r"(dst), "l"(src));
}
__device__ __forceinline__ void cpa_commit() {
    asm volatile("cp.async.commit_group;" ::: "memory");
}
template <int N>
__device__ __forceinline__ void cpa_wait() {
    asm volatile("cp.async.wait_group %0;" :: "n"(N) : "memory");
}

#define HSTRIDE 40                       // halfs per row (80 B)
#define BUFB (128 * HSTRIDE * 2)         // bytes per stage buffer = 10240
#define NSTAGE 4
#define GEMM_DYN (2 * NSTAGE * BUFB)     // A stages + B stages = 81920 bytes

// ---------------- fp16 mma GEMM: 2 CTA/SM, 4-stage pipeline, rotated fragment prefetch ----------------
__global__ void __launch_bounds__(256, 2) gemm_mma(const int* __restrict__ labels) {
    extern __shared__ __align__(16) char dynsm[];
    __shared__ int s_rall[128], s_rsem[128], s_call[128], s_csem[128];
    __shared__ float s_sqi[128], s_sqj[128], s_hp2i[128], s_hp2j[128];
    __shared__ int s_li[128], s_lj[128];

    int rem = blockIdx.x, by = 0;
    while (rem >= TILES - by) { rem -= TILES - by; by++; }
    const int bx = by + rem;
    const bool diag = (bx == by);
    const int rowBase = by * 128;
    const int colBase = bx * 128;

    const int tid = threadIdx.x;
    const int wid = tid >> 5;
    const int lane = tid & 31;
    const int g = lane >> 2;
    const int t = lane & 3;
    const int mBase = (wid >> 2) * 64;
    const int nBase = (wid & 3) * 32;

    if (tid < 128) {
        s_rall[tid] = 0x7F800000; s_rsem[tid] = 0x7F800000;
        s_call[tid] = 0x7F800000; s_csem[tid] = 0x7F800000;
        const int gi = rowBase + tid, gj = colBase + tid;
        s_sqi[tid] = g_sq[gi]; s_hp2i[tid] = g_hp2[gi]; s_li[tid] = labels[gi];
        s_sqj[tid] = g_sq[gj]; s_hp2j[tid] = g_hp2[gj]; s_lj[tid] = labels[gj];
    }

    float acc[4][4][4];
    #pragma unroll
    for (int mf = 0; mf < 4; mf++)
        #pragma unroll
        for (int nf = 0; nf < 4; nf++)
            #pragma unroll
            for (int r = 0; r < 4; r++) acc[mf][nf][r] = 0.f;

    const int prow = tid >> 2;
    const int pseg = tid & 3;
    const uint32_t AshD = (uint32_t)__cvta_generic_to_shared(dynsm);
    const uint32_t BshD = AshD + NSTAGE * BUFB;
    const half* srcA = g_embh + (size_t)(rowBase + prow) * DDIM + pseg * 8;
    const half* srcB = g_embh + (size_t)(colBase + prow) * DDIM + pseg * 8;
    const uint32_t dstOff = prow * 80 + pseg * 16;

    const int arow = (lane & 7) + (((lane >> 3) & 1) << 3);
    const int acol = (lane >> 4) << 3;
    const int brow = ((lane >> 4) << 3) + (lane & 7);
    const int bcol = ((lane >> 3) & 1) << 3;
    const uint32_t aBase0 = AshD + (((mBase + arow) * HSTRIDE + acol) << 1);
    const uint32_t bBase0 = (diag ? AshD : BshD) + (((nBase + brow) * HSTRIDE + bcol) << 1);

    auto issue = [&](int c) {
        const int st = c & (NSTAGE - 1);
        const int k0 = c * 32;
        #pragma unroll
        for (int q = 0; q < 2; q++) {
            cpa16(AshD + st * BUFB + dstOff + q * 64 * 80, srcA + (size_t)(q * 64) * DDIM + k0);
            if (!diag)
                cpa16(BshD + st * BUFB + dstOff + q * 64 * 80, srcB + (size_t)(q * 64) * DDIM + k0);
        }
        cpa_commit();
    };

    issue(0); issue(1); issue(2);

    #pragma unroll
    for (int c = 0; c < 16; c++) {
        if (c < 14)       cpa_wait<2>();
        else if (c == 14) cpa_wait<1>();
        else              cpa_wait<0>();
        __syncthreads();
        if (c + 3 < 16) issue(c + 3);

        const int st = c & (NSTAGE - 1);
        const uint32_t aCh = aBase0 + st * BUFB;
        const uint32_t bCh = bBase0 + st * BUFB;

        // rotated prefetch: load A(mf+1)/B(s=1) while mma(mf) runs
        uint32_t bf[2][4][2];    // [s][nf][reg]
        uint32_t af[2][4];       // double buffer by mf parity
        ldsm4(bf[0][0][0], bf[0][0][1], bf[0][1][0], bf[0][1][1], bCh);
        ldsm4(bf[0][2][0], bf[0][2][1], bf[0][3][0], bf[0][3][1], bCh + ((16 * HSTRIDE) << 1));
        ldsm4(af[0][0], af[0][1], af[0][2], af[0][3], aCh);

        #pragma unroll
        for (int s = 0; s < 2; s++) {
            #pragma unroll
            for (int mf = 0; mf < 4; mf++) {
                uint32_t* cur = af[mf & 1];
                uint32_t* nxt = af[(mf + 1) & 1];
                if (mf < 3) {
                    const uint32_t aaddr = aCh + (((mf + 1) * 16 * HSTRIDE + s * 16) << 1);
                    ldsm4(nxt[0], nxt[1], nxt[2], nxt[3], aaddr);
                } else if (s == 0) {
                    ldsm4(bf[1][0][0], bf[1][0][1], bf[1][1][0], bf[1][1][1], bCh + 32);
                    ldsm4(bf[1][2][0], bf[1][2][1], bf[1][3][0], bf[1][3][1],
                          bCh + ((16 * HSTRIDE) << 1) + 32);
                    ldsm4(nxt[0], nxt[1], nxt[2], nxt[3], aCh + 32);
                }
                #pragma unroll
                for (int nf = 0; nf < 4; nf++)
                    mma16(acc[mf][nf], cur, bf[s][nf]);
            }
        }
    }

    // ---------------- epilogue ----------------
    float rAll[4][2], rSem[4][2], cAll[4][2], cSem[4][2];
    #pragma unroll
    for (int x = 0; x < 4; x++)
        #pragma unroll
        for (int y = 0; y < 2; y++) {
            rAll[x][y] = CUDART_INF_F; rSem[x][y] = CUDART_INF_F;
            cAll[x][y] = CUDART_INF_F; cSem[x][y] = CUDART_INF_F;
        }

    #pragma unroll
    for (int mf = 0; mf < 4; mf++) {
        #pragma unroll
        for (int h = 0; h < 2; h++) {
            const int rloc = mBase + mf * 16 + g + 8 * h;
            const float sqi = s_sqi[rloc];
            const int li = s_li[rloc];
            const float hp2i = s_hp2i[rloc];
            #pragma unroll
            for (int nf = 0; nf < 4; nf++) {
                #pragma unroll
                for (int b = 0; b < 2; b++) {
                    const int cloc = nBase + nf * 8 + 2 * t + b;
                    const float dot = acc[mf][nf][2 * h + b];
                    const float v = fmaxf(sqi + s_sqj[cloc] - 2.f * dot, 0.f);
                    const bool neg = (li != s_lj[cloc]);
                    const float va = neg ? v : CUDART_INF_F;
                    const float vsr = (neg && v > hp2i) ? v : CUDART_INF_F;
                    const float vsc = (neg && v > s_hp2j[cloc]) ? v : CUDART_INF_F;
                    rAll[mf][h] = fminf(rAll[mf][h], va);
                    rSem[mf][h] = fminf(rSem[mf][h], vsr);
                    cAll[nf][b] = fminf(cAll[nf][b], va);
                    cSem[nf][b] = fminf(cSem[nf][b], vsc);
                }
            }
        }
    }

    #pragma unroll
    for (int mf = 0; mf < 4; mf++)
        #pragma unroll
        for (int h = 0; h < 2; h++) {
            float a = rAll[mf][h], s = rSem[mf][h];
            #pragma unroll
            for (int o = 1; o < 4; o <<= 1) {
                a = fminf(a, __shfl_xor_sync(0xFFFFFFFF, a, o));
                s = fminf(s, __shfl_xor_sync(0xFFFFFFFF, s, o));
            }
            if (t == 0) {
                const int rloc = mBase + mf * 16 + g + 8 * h;
                atomicMin(&s_rall[rloc], __float_as_int(a));
                atomicMin(&s_rsem[rloc], __float_as_int(s));
            }
        }
    #pragma unroll
    for (int nf = 0; nf < 4; nf++)
        #pragma unroll
        for (int b = 0; b < 2; b++) {
            float a = cAll[nf][b], s = cSem[nf][b];
            #pragma unroll
            for (int o = 4; o < 32; o <<= 1) {
                a = fminf(a, __shfl_xor_sync(0xFFFFFFFF, a, o));
                s = fminf(s, __shfl_xor_sync(0xFFFFFFFF, s, o));
            }
            if (g == 0) {
                const int cloc = nBase + nf * 8 + 2 * t + b;
                atomicMin(&s_call[cloc], __float_as_int(a));
                atomicMin(&s_csem[cloc], __float_as_int(s));
            }
        }
    __syncthreads();

    if (tid < 128) {
        g_all2[(size_t)bx * BDIM + rowBase + tid] = __int_as_float(s_rall[tid]);
        g_semi2[(size_t)bx * BDIM + rowBase + tid] = __int_as_float(s_rsem[tid]);
        if (!diag) {
            g_all2[(size_t)by * BDIM + colBase + tid] = __int_as_float(s_call[tid]);
            g_semi2[(size_t)by * BDIM + colBase + tid] = __int_as_float(s_csem[tid]);
        }
    }
}

// ---------------- per-row finish ----------------
__global__ void __launch_bounds__(256) rowfinish() {
    const int r = blockIdx.x * 256 + threadIdx.x;
    float mA = CUDART_INF_F, mS = CUDART_INF_F;
    #pragma unroll 8
    for (int tt = 0; tt < TILES; tt++) {
        mA = fminf(mA, g_all2[(size_t)tt * BDIM + r]);
        mS = fminf(mS, g_semi2[(size_t)tt * BDIM + r]);
    }
    const float hn2 = (mS < CUDART_INF_F) ? mS : mA;
    const float hp2 = g_hp2[r];
    float loss = 0.f;
    if (hp2 >= 0.f) {
        const float l = sqrtf(hp2) - sqrtf(hn2) + MARGIN;
        loss = fmaxf(l, 0.f);
    }
    g_loss[r] = loss;
}

__global__ void __launch_bounds__(256) final_reduce(float* __restrict__ out) {
    const int tid = threadIdx.x;
    float acc = 0.f;
    for (int k = tid; k < BDIM; k += 256) acc += g_loss[k];
    __shared__ float s[256];
    s[tid] = acc;
    __syncthreads();
    #pragma unroll
    for (int st = 128; st > 0; st >>= 1) {
        if (tid < st) s[tid] += s[tid + st];
        __syncthreads();
    }
    if (tid == 0) out[0] = s[0] / (float)BDIM;
}

// ---------------- launch ----------------
extern "C" void kernel_launch(void* const* d_in, const int* in_sizes, int n_in,
                              void* d_out, int out_size) {
    const float* emb = (const float*)d_in[0];
    const int* labels = (const int*)d_in[1];
    float* out = (float*)d_out;

    cudaFuncSetAttribute(hp_kernel, cudaFuncAttributeMaxDynamicSharedMemorySize, HPBYTES);
    cudaFuncSetAttribute(gemm_mma, cudaFuncAttributeMaxDynamicSharedMemorySize, GEMM_DYN);

    prep_kernel<<<BDIM, 128>>>(emb);
    scatter_cls<<<BDIM / 256, 256>>>(labels);
    hp_kernel<<<512, 256, HPBYTES>>>();
    gemm_mma<<<NTRI, 256, GEMM_DYN>>>(labels);
    rowfinish<<<BDIM / 256, 256>>>();
    final_reduce<<<1, 256>>>(out);
}